// round 7
// baseline (speedup 1.0000x reference)
#include <cuda_runtime.h>
#include <cuda_bf16.h>

#define NNODE 128
#define NM1   127            // edges per receiver
#define NRR   (NNODE * NM1)  // 16256 directed edges
#define BB    128
#define CC    16

// One CTA per (batch b, receiver r). 128 threads; thread t owns edge
// (r*127 + t) for t < 127 (thread 127 is padding and contributes 0).
// Pass structure:
//   1. vectorized load of 16 channels into registers (raw x kept)
//   2. __expf per element
//   3. per-channel butterfly reduction across warp, 4-warp combine in smem
//   4. 16 threads compute reciprocal of the group denominator
//   5. out[b][c][r*127+t] = x * rden[c]  (warp-coalesced per channel)
__global__ __launch_bounds__(128) void attention2_denom_kernel(
    const float* __restrict__ x, float* __restrict__ out)
{
    const int r    = blockIdx.x;
    const int b    = blockIdx.y;
    const int t    = threadIdx.x;
    const int lane = t & 31;
    const int warp = t >> 5;

    __shared__ float ws[4][CC];
    __shared__ float rden_s[CC];

    float v[CC];
    float e[CC];
    const bool active = (t < NM1);

    const float4* src = reinterpret_cast<const float4*>(
        x + ((size_t)b * NRR + (size_t)r * NM1 + (size_t)t) * CC);

    if (active) {
        #pragma unroll
        for (int j = 0; j < 4; j++) {
            float4 q = src[j];
            v[4*j+0] = q.x; v[4*j+1] = q.y;
            v[4*j+2] = q.z; v[4*j+3] = q.w;
        }
        #pragma unroll
        for (int i = 0; i < CC; i++) e[i] = __expf(v[i]);
    } else {
        #pragma unroll
        for (int i = 0; i < CC; i++) { v[i] = 0.f; e[i] = 0.f; }
    }

    // Per-channel sum across the 32 lanes of each warp.
    #pragma unroll
    for (int i = 0; i < CC; i++) {
        float s = e[i];
        s += __shfl_xor_sync(0xffffffffu, s, 16);
        s += __shfl_xor_sync(0xffffffffu, s, 8);
        s += __shfl_xor_sync(0xffffffffu, s, 4);
        s += __shfl_xor_sync(0xffffffffu, s, 2);
        s += __shfl_xor_sync(0xffffffffu, s, 1);
        e[i] = s;
    }
    if (lane == 0) {
        #pragma unroll
        for (int i = 0; i < CC; i++) ws[warp][i] = e[i];
    }
    __syncthreads();

    // One reciprocal per channel for the whole group (not per element).
    if (t < CC) {
        float d = ws[0][t] + ws[1][t] + ws[2][t] + ws[3][t];
        rden_s[t] = __frcp_rn(d);
    }
    __syncthreads();

    if (active) {
        float* o = out + (size_t)b * CC * NRR + (size_t)r * NM1 + (size_t)t;
        #pragma unroll
        for (int c = 0; c < CC; c++) {
            // For fixed c, lanes t..t+31 write 128 contiguous bytes.
            o[(size_t)c * NRR] = v[c] * rden_s[c];
        }
    }
}

extern "C" void kernel_launch(void* const* d_in, const int* in_sizes, int n_in,
                              void* d_out, int out_size)
{
    // d_in[0]: x  float32 [B, NR, C]
    // d_in[1]: receivers int32 [NR] — structurally i/(N-1), not needed
    const float* x   = (const float*)d_in[0];
    float*       out = (float*)d_out;   // float32 [B, C, NR]

    dim3 grid(NNODE, BB);   // (receiver, batch)
    attention2_denom_kernel<<<grid, 128>>>(x, out);
}

// round 8
// speedup vs baseline: 1.2355x; 1.2355x over previous
#include <cuda_runtime.h>
#include <cuda_bf16.h>

#define NNODE 128
#define NM1   127            // edges per receiver
#define NRR   (NNODE * NM1)  // 16256 directed edges
#define BB    128
#define CC    16

// SW128-style smem swizzle on byte offsets: XOR bits [9:7] into [6:4].
// Keeps 16B accesses within their 128B row; makes both the phase-1
// (8 consecutive float4s) and phase-2 (stride-4 float4 column) patterns
// bank-conflict-free.
__device__ __forceinline__ unsigned swz(unsigned byte_off) {
    return byte_off ^ ((byte_off >> 3) & 0x70u);
}

// One CTA per (batch b, receiver r), 128 threads.
//
// Phase 1 (scrambled ownership, perfectly coalesced loads):
//   thread t loads float4 #(t + 128j), j=0..3, of the CTA's 508-float4
//   chunk (127 edges x 16 ch). Every LDG.128 is a contiguous 512B warp
//   transaction. Thread's channel-quad q = t&3 is constant across j, so
//   it accumulates exp() into one float4 acc.
// Reduction: xor-shuffle over lanes sharing q (masks 4,8,16) covers all
//   32 edges of the warp; 4-warp combine through 256B of smem; 16 threads
//   compute one reciprocal per channel.
// Phase 2 (edge ownership, optimal stores):
//   raw x was staged in swizzled smem; thread t (= edge t) reads its 16
//   channels back (4 conflict-free LDS.128), scales by rden, and issues
//   16 warp-coalesced STG.32 (128B runs per channel — the best possible
//   store shape given the 127-stride misalignment).
__global__ __launch_bounds__(128) void attention2_denom_kernel(
    const float* __restrict__ x, float* __restrict__ out)
{
    const int r    = blockIdx.x;
    const int b    = blockIdx.y;
    const int t    = threadIdx.x;
    const int warp = t >> 5;
    const int lane = t & 31;

    __shared__ __align__(16) unsigned char v_s[NM1 * CC * 4 + 64]; // 8128B staged x
    __shared__ float4 ws4[4][4];     // per-warp exp sums: ws4[w][q] = ch 4q..4q+3
    __shared__ float4 rden4[4];      // reciprocal denominators, 16 channels

    const float4* __restrict__ src =
        reinterpret_cast<const float4*>(x + ((size_t)b * NRR + (size_t)r * NM1) * CC);

    // ---- Phase 1: coalesced load, exp, stage, accumulate -------------------
    float4 acc = make_float4(0.f, 0.f, 0.f, 0.f);
    #pragma unroll
    for (int j = 0; j < 4; j++) {
        int f = t + 128 * j;                 // float4 index in [0, 508)
        if (f < NM1 * 4) {                   // j=3 predicated (t < 124)
            float4 g = src[f];
            acc.x += __expf(g.x);
            acc.y += __expf(g.y);
            acc.z += __expf(g.z);
            acc.w += __expf(g.w);
            *reinterpret_cast<float4*>(v_s + swz((unsigned)(16 * f))) = g;
        }
    }

    // ---- Reduce over edges: lanes with equal q = t&3 (masks 4,8,16) --------
    #pragma unroll
    for (int m = 4; m <= 16; m <<= 1) {
        acc.x += __shfl_xor_sync(0xffffffffu, acc.x, m);
        acc.y += __shfl_xor_sync(0xffffffffu, acc.y, m);
        acc.z += __shfl_xor_sync(0xffffffffu, acc.z, m);
        acc.w += __shfl_xor_sync(0xffffffffu, acc.w, m);
    }
    if (lane < 4) ws4[warp][lane] = acc;     // lane == its quad q
    __syncthreads();

    if (t < CC) {
        const float* wsf = reinterpret_cast<const float*>(ws4);
        float d = wsf[0 * CC + t] + wsf[1 * CC + t]
                + wsf[2 * CC + t] + wsf[3 * CC + t];
        reinterpret_cast<float*>(rden4)[t] = __frcp_rn(d);
    }
    __syncthreads();

    // ---- Phase 2: edge-owned readback + coalesced transposed stores --------
    if (t < NM1) {
        float4 rd0 = rden4[0], rd1 = rden4[1], rd2 = rden4[2], rd3 = rden4[3];
        float4 v0 = *reinterpret_cast<const float4*>(v_s + swz((unsigned)(16 * (4 * t + 0))));
        float4 v1 = *reinterpret_cast<const float4*>(v_s + swz((unsigned)(16 * (4 * t + 1))));
        float4 v2 = *reinterpret_cast<const float4*>(v_s + swz((unsigned)(16 * (4 * t + 2))));
        float4 v3 = *reinterpret_cast<const float4*>(v_s + swz((unsigned)(16 * (4 * t + 3))));

        float* o = out + (size_t)b * CC * NRR + (size_t)r * NM1 + (size_t)t;
        o[ 0 * NRR] = v0.x * rd0.x;  o[ 1 * NRR] = v0.y * rd0.y;
        o[ 2 * NRR] = v0.z * rd0.z;  o[ 3 * NRR] = v0.w * rd0.w;
        o[ 4 * NRR] = v1.x * rd1.x;  o[ 5 * NRR] = v1.y * rd1.y;
        o[ 6 * NRR] = v1.z * rd1.z;  o[ 7 * NRR] = v1.w * rd1.w;
        o[ 8 * NRR] = v2.x * rd2.x;  o[ 9 * NRR] = v2.y * rd2.y;
        o[10 * NRR] = v2.z * rd2.z;  o[11 * NRR] = v2.w * rd2.w;
        o[12 * NRR] = v3.x * rd3.x;  o[13 * NRR] = v3.y * rd3.y;
        o[14 * NRR] = v3.z * rd3.z;  o[15 * NRR] = v3.w * rd3.w;
    }
}

extern "C" void kernel_launch(void* const* d_in, const int* in_sizes, int n_in,
                              void* d_out, int out_size)
{
    // d_in[0]: x  float32 [B, NR, C]
    // d_in[1]: receivers int32 [NR] — structurally i/(N-1), unused
    const float* x   = (const float*)d_in[0];
    float*       out = (float*)d_out;   // float32 [B, C, NR]

    dim3 grid(NNODE, BB);   // (receiver, batch)
    attention2_denom_kernel<<<grid, 128>>>(x, out);
}